// round 1
// baseline (speedup 1.0000x reference)
#include <cuda_runtime.h>
#include <math.h>

#define B_ 64
#define C_ 3
#define N_ 512
#define CUT_ 4

__global__ void __launch_bounds__(256)
diffeo_kernel(const float* __restrict__ x,
              const float* __restrict__ Fx,
              const float* __restrict__ Fy,
              float* __restrict__ out,
              float scale) {
    __shared__ float sGx[16];
    __shared__ float sGy[16];

    const int b  = blockIdx.z;
    const int y  = blockIdx.y;
    const int xi = blockIdx.x * blockDim.x + threadIdx.x;

    if (threadIdx.x < 16) {
        int i = threadIdx.x >> 2;       // coeff row index (k_i = i+1)
        int j = threadIdx.x & 3;        // coeff col index (k_j = j+1)
        float ki = (float)(i + 1);
        float kj = (float)(j + 1);
        float r  = sqrtf(ki * ki + kj * kj);
        float e  = (r < (float)CUT_ + 0.5f) ? (1.0f / r) : 0.0f;
        sGx[threadIdx.x] = Fx[b * 16 + threadIdx.x] * e;
        sGy[threadIdx.x] = Fy[b * 16 + threadIdx.x] * e;
    }
    __syncthreads();

    // s[p, k] = sin(pi * p/(n-1) * k), k = 1..4
    const float inv = 1.0f / (float)(N_ - 1);
    const float px  = (float)xi * inv * (float)M_PI;
    const float py  = (float)y  * inv * (float)M_PI;

    float sx[4], sy[4];
#pragma unroll
    for (int k = 0; k < 4; k++) {
        sx[k] = __sinf(px * (float)(k + 1));
        sy[k] = __sinf(py * (float)(k + 1));
    }

    // field[b,y,x] = sum_{i,j} G[b,i,j] * sx[i] * sy[j]
    float u = 0.0f, v = 0.0f;
#pragma unroll
    for (int j = 0; j < 4; j++) {
        float ax = 0.0f, ay = 0.0f;
#pragma unroll
        for (int i = 0; i < 4; i++) {
            ax = fmaf(sGx[i * 4 + j], sx[i], ax);
            ay = fmaf(sGy[i * 4 + j], sx[i], ay);
        }
        u = fmaf(ax, sy[j], u);
        v = fmaf(ay, sy[j], v);
    }

    const float dx = scale * u;
    const float dy = scale * v;

    float xn = fminf(fmaxf((float)xi - dx, 0.0f), (float)(N_ - 1));
    float yn = fminf(fmaxf((float)y  - dy, 0.0f), (float)(N_ - 1));

    float xff = floorf(xn), yff = floorf(yn);
    int xf = (int)xff;
    int yf = (int)yff;
    int xc = (int)ceilf(xn);
    int yc = (int)ceilf(yn);
    float xv = xn - xff;
    float yv = yn - yff;

    float w00 = (1.0f - yv) * (1.0f - xv);
    float w01 = (1.0f - yv) * xv;
    float w10 = yv * (1.0f - xv);
    float w11 = yv * xv;

    const size_t img_stride = (size_t)N_ * N_;
    const float* img = x + (size_t)b * C_ * img_stride;
    float* o = out + (size_t)b * C_ * img_stride + (size_t)y * N_ + xi;

    const size_t o00 = (size_t)yf * N_ + xf;
    const size_t o01 = (size_t)yf * N_ + xc;
    const size_t o10 = (size_t)yc * N_ + xf;
    const size_t o11 = (size_t)yc * N_ + xc;

#pragma unroll
    for (int c = 0; c < C_; c++) {
        const float* im = img + (size_t)c * img_stride;
        float val = w00 * __ldg(im + o00)
                  + w01 * __ldg(im + o01)
                  + w10 * __ldg(im + o10)
                  + w11 * __ldg(im + o11);
        o[(size_t)c * img_stride] = val;
    }
}

extern "C" void kernel_launch(void* const* d_in, const int* in_sizes, int n_in,
                              void* d_out, int out_size) {
    const float* x  = (const float*)d_in[0];
    const float* Fx = (const float*)d_in[1];
    const float* Fy = (const float*)d_in[2];
    float* out = (float*)d_out;

    // typ = n * sqrt(pi * log(cut)) / 2 ; scale = sqrt(T/typ^2) * n
    const double n_d   = (double)N_;
    const double typ   = n_d * sqrt(M_PI * log((double)CUT_)) / 2.0;
    const double T     = 0.01;
    const float scale  = (float)(sqrt(T / (typ * typ)) * n_d);

    dim3 block(256);
    dim3 grid(N_ / 256, N_, B_);
    diffeo_kernel<<<grid, block>>>(x, Fx, Fy, out, scale);
}

// round 2
// speedup vs baseline: 1.6396x; 1.6396x over previous
#include <cuda_runtime.h>
#include <math.h>

#define B_ 64
#define C_ 3
#define N_ 512

__global__ void __launch_bounds__(256)
diffeo_kernel(const float* __restrict__ x,
              const float* __restrict__ Fx,
              const float* __restrict__ Fy,
              float* __restrict__ out,
              float scale) {
    __shared__ float gsh[8];   // [0..3]=gu_i, [4..7]=gv_i

    const int y   = blockIdx.x;
    const int b   = blockIdx.y;
    const int tid = threadIdx.x;

    const float PI_INV = (float)M_PI / (float)(N_ - 1);

    // 8 threads: fold y-dependence + envelope into 4 coeffs per field.
    // g_i = sum_j F[b,i,j] * e[i,j] * sin(pi*y/(n-1)*(j+1))
    if (tid < 8) {
        const int  i   = tid & 3;          // x-harmonic index
        const int  isV = tid >> 2;
        const float* F = (isV ? Fy : Fx) + b * 16 + i * 4;
        const float py = (float)y * PI_INV;
        const float ki = (float)(i + 1);
        float acc = 0.0f;
#pragma unroll
        for (int j = 0; j < 4; j++) {
            float kj = (float)(j + 1);
            float r  = sqrtf(ki * ki + kj * kj);
            float e  = (r < 4.5f) ? (1.0f / r) : 0.0f;
            float sj = __sinf(py * (float)(j + 1));
            acc = fmaf(F[j] * e, sj, acc);
        }
        gsh[tid] = acc;
    }
    __syncthreads();

    const float gu0 = gsh[0], gu1 = gsh[1], gu2 = gsh[2], gu3 = gsh[3];
    const float gv0 = gsh[4], gv1 = gsh[5], gv2 = gsh[6], gv3 = gsh[7];

    const size_t img_stride = (size_t)N_ * N_;
    const float* img  = x   + (size_t)b * C_ * img_stride;
    float*       obase = out + (size_t)b * C_ * img_stride + (size_t)y * N_;

    const int   x0 = tid * 2;
    const float fy = (float)y;

    float r0[2], r1[2], r2[2];

#pragma unroll
    for (int k = 0; k < 2; k++) {
        const int   xi = x0 + k;
        const float p  = (float)xi * PI_INV;

        // sin(k*p) for k=1..4 via double-angle (2 MUFU + ~6 flops)
        const float s1 = __sinf(p);
        const float c1 = __cosf(p);
        const float s2 = 2.0f * s1 * c1;
        const float c2 = fmaf(2.0f * c1, c1, -1.0f);
        const float s3 = fmaf(s1, c2, c1 * s2);
        const float s4 = 2.0f * s2 * c2;

        const float u = fmaf(gu0, s1, fmaf(gu1, s2, fmaf(gu2, s3, gu3 * s4)));
        const float v = fmaf(gv0, s1, fmaf(gv1, s2, fmaf(gv2, s3, gv3 * s4)));

        float xn = fminf(fmaxf((float)xi - scale * u, 0.0f), (float)(N_ - 1));
        float yn = fminf(fmaxf(fy        - scale * v, 0.0f), (float)(N_ - 1));

        const float xff = floorf(xn);
        const float yff = floorf(yn);
        const int   xf  = (int)xff;
        const int   yf  = (int)yff;
        const float xv  = xn - xff;
        const float yv  = yn - yff;

        // ceil == floor+1 clamped; when xn is integer the weight is exactly 0,
        // so the clamped tap value never contributes.
        const int dxB = (xf < N_ - 1) ? 4        : 0;   // byte step to x+1
        const int dyB = (yf < N_ - 1) ? 4 * N_   : 0;   // byte step to y+1

        const float w00 = (1.0f - yv) * (1.0f - xv);
        const float w01 = (1.0f - yv) * xv;
        const float w10 = yv * (1.0f - xv);
        const float w11 = yv * xv;

        const char* a00 = (const char*)(img + (size_t)yf * N_ + xf);
        const char* a01 = a00 + dxB;
        const char* a10 = a00 + dyB;
        const char* a11 = a10 + dxB;

#pragma unroll
        for (int c = 0; c < C_; c++) {
            const size_t cb = (size_t)c * img_stride * sizeof(float);
            float t00 = __ldg((const float*)(a00 + cb));
            float t01 = __ldg((const float*)(a01 + cb));
            float t10 = __ldg((const float*)(a10 + cb));
            float t11 = __ldg((const float*)(a11 + cb));
            float val = fmaf(w00, t00, fmaf(w01, t01, fmaf(w10, t10, w11 * t11)));
            if (c == 0) r0[k] = val;
            else if (c == 1) r1[k] = val;
            else r2[k] = val;
        }
    }

    // coalesced vector stores, one per channel
    *(float2*)(obase + 0 * img_stride + x0) = make_float2(r0[0], r0[1]);
    *(float2*)(obase + 1 * img_stride + x0) = make_float2(r1[0], r1[1]);
    *(float2*)(obase + 2 * img_stride + x0) = make_float2(r2[0], r2[1]);
}

extern "C" void kernel_launch(void* const* d_in, const int* in_sizes, int n_in,
                              void* d_out, int out_size) {
    const float* x  = (const float*)d_in[0];
    const float* Fx = (const float*)d_in[1];
    const float* Fy = (const float*)d_in[2];
    float* out = (float*)d_out;

    const double n_d  = (double)N_;
    const double typ  = n_d * sqrt(M_PI * log(4.0)) / 2.0;
    const double T    = 0.01;
    const float scale = (float)(sqrt(T / (typ * typ)) * n_d);

    dim3 block(256);
    dim3 grid(N_, B_);   // one row per block
    diffeo_kernel<<<grid, block>>>(x, Fx, Fy, out, scale);
}